// round 14
// baseline (speedup 1.0000x reference)
#include <cuda_runtime.h>
#include <cuda_fp16.h>
#include <cstdint>

// PolyConv: scan-free CSR build (warp-aggregated row alloc) + fused
// rows/fac/init + atomic-free 4-lane-group iterations.
// State fp32 in-place; gather fp32 (iter1) then fp16 ping-pong (iters 2-4).
// h deferred: first written in iter2 (pure write from s0,s1,s2).
// Inputs: feat [N*32 f32], src [E i32], dst [E i32], mask [E f32]
// Output: h [N*32 f32]

#define N_NODES 100000
#define N_EDGES 1600000
#define DFEAT   32
#define DV4     (DFEAT / 4)        // 8 float4 per node row
#define NV4     (N_NODES * DV4)
#define NH4     (N_NODES * 4)      // 4 uint4 (8 halves) per node row

// ---- scratch (static __device__, zero-initialized; every call restores zeros) ----
__device__ int    g_cnt[N_NODES];        // in-degree; re-zeroed in iter4 tail
__device__ float  g_degf[N_NODES];       // mask-sum;  re-zeroed in iter4 tail
__device__ int    g_total;               // row allocator; re-zeroed in iter4 tail
__device__ int2   g_rows[N_NODES];       // {base, end} of node's CSR segment
__device__ int    g_cursor[N_NODES];
__device__ float2 g_fac[N_NODES];        // {dinv^2, sqrt(max(deg,1))}
__device__ int2   g_edges[N_EDGES];      // CSR: {src, mask_bits} grouped by dst
__device__ float4 g_src32[NV4];          // fp32 gather source for iter1 (T0 scaled)
__device__ float4 g_scaled[NV4];         // fp32 state, in-place (row-major)
__device__ uint4  g_halfA[NH4];          // fp16 gather mirror (ping)
__device__ uint4  g_halfB[NH4];          // fp16 gather mirror (pong)

static __device__ __forceinline__ unsigned h2u(__half2 h) {
    return *reinterpret_cast<unsigned*>(&h);
}

// ---------------------------------------------------------------------------
// histogram: edge count + mask-sum per dst (both start zero: invariant)
__global__ void k_hist(const int* __restrict__ dst, const float* __restrict__ mask, int E) {
    int e = blockIdx.x * blockDim.x + threadIdx.x;
    if (e < E) {
        int d = dst[e];
        atomicAdd(&g_cnt[d], 1);
        atomicAdd(&g_degf[d], mask[e]);
    }
}

// rows + factors + init fused.
// Phase 1 (thread per node): warp-aggregated atomic row allocation, fac from degf.
// Phase 2 (block-stride): src32 = feat * dinv (coalesced float4 writes).
__global__ void __launch_bounds__(256)
k_rows_init(const float4* __restrict__ feat4) {
    __shared__ float sh_dinv[256];
    int t = threadIdx.x;
    int lane = t & 31;
    int nb = blockIdx.x * 256;           // node base for this block
    int n = nb + t;

    int cnt = (n < N_NODES) ? g_cnt[n] : 0;

    // warp-inclusive scan of cnt
    int incl = cnt;
    #pragma unroll
    for (int o = 1; o < 32; o <<= 1) {
        int y = __shfl_up_sync(0xFFFFFFFFu, incl, o);
        if (lane >= o) incl += y;
    }
    int warp_base = 0;
    if (lane == 31) warp_base = atomicAdd(&g_total, incl);   // incl == warp total
    warp_base = __shfl_sync(0xFFFFFFFFu, warp_base, 31);

    float dinv = 0.0f;
    if (n < N_NODES) {
        int base = warp_base + incl - cnt;
        g_rows[n] = make_int2(base, base + cnt);
        g_cursor[n] = base;
        float deg = fmaxf(g_degf[n], 1.0f);
        dinv = rsqrtf(deg);
        g_fac[n] = make_float2(dinv * dinv, deg * dinv);     // {dinv^2, sqrt(deg)}
    }
    sh_dinv[t] = dinv;
    __syncthreads();

    // Phase 2: 256 nodes x 8 float4 = 2048 float4, block-stride coalesced
    for (int i = t; i < 256 * DV4; i += 256) {
        int nn = nb + (i >> 3);
        if (nn >= N_NODES) break;
        float dv = sh_dinv[i >> 3];
        int idx = nn * DV4 + (i & 7);
        float4 f = feat4[idx];
        float4 s;
        s.x = f.x * dv; s.y = f.y * dv; s.z = f.z * dv; s.w = f.w * dv;
        g_src32[idx] = s;
    }
}

__global__ void k_scatter(const int* __restrict__ src, const int* __restrict__ dst,
                          const float* __restrict__ mask, int E) {
    int e = blockIdx.x * blockDim.x + threadIdx.x;
    if (e >= E) return;
    int d = dst[e];
    int pos = atomicAdd(&g_cursor[d], 1);
    g_edges[pos] = make_int2(src[e], __float_as_int(mask[e]));
}

// iteration 1: fp32 gather from src32; writes fp32 state + fp16 mirror. NO h.
__global__ void __launch_bounds__(256)
k_iter1() {
    int t = threadIdx.x;
    int n = blockIdx.x * 64 + (t >> 2);
    if (n >= N_NODES) return;
    int c = t & 3;

    int2 rr = g_rows[n];

    float a0 = 0.f, a1 = 0.f, a2 = 0.f, a3 = 0.f;
    float a4 = 0.f, a5 = 0.f, a6 = 0.f, a7 = 0.f;

    #pragma unroll 2
    for (int j = rr.x; j < rr.y; ++j) {
        int2 ed = g_edges[j];
        float m = __int_as_float(ed.y);
        const float4* p = &g_src32[ed.x * DV4 + c * 2];
        float4 v0 = p[0], v1 = p[1];
        a0 += v0.x * m; a1 += v0.y * m; a2 += v0.z * m; a3 += v0.w * m;
        a4 += v1.x * m; a5 += v1.y * m; a6 += v1.z * m; a7 += v1.w * m;
    }

    float2 fac = g_fac[n];
    float dinv2 = fac.x;

    int i0 = n * DV4 + c * 2;
    float4 o0 = g_src32[i0], o1 = g_src32[i0 + 1];
    float4 s0, s1;
    s0.x = o0.x - a0 * dinv2; s0.y = o0.y - a1 * dinv2;
    s0.z = o0.z - a2 * dinv2; s0.w = o0.w - a3 * dinv2;
    s1.x = o1.x - a4 * dinv2; s1.y = o1.y - a5 * dinv2;
    s1.z = o1.z - a6 * dinv2; s1.w = o1.w - a7 * dinv2;
    g_scaled[i0] = s0;
    g_scaled[i0 + 1] = s1;

    uint4 hp;
    hp.x = h2u(__floats2half2_rn(s0.x, s0.y));
    hp.y = h2u(__floats2half2_rn(s0.z, s0.w));
    hp.z = h2u(__floats2half2_rn(s1.x, s1.y));
    hp.w = h2u(__floats2half2_rn(s1.z, s1.w));
    g_halfB[n * 4 + c] = hp;
}

// iteration 2: fp16 gather from halfB; h PURE WRITE = rsq*(th0*s0 + th1*s1 + th2*s2);
// state update in place; writes halfA mirror.
__global__ void __launch_bounds__(256)
k_iter2(float4* __restrict__ h4, float th0, float th1, float th2) {
    int t = threadIdx.x;
    int n = blockIdx.x * 64 + (t >> 2);
    if (n >= N_NODES) return;
    int c = t & 3;

    int2 rr = g_rows[n];

    float a0 = 0.f, a1 = 0.f, a2 = 0.f, a3 = 0.f;
    float a4 = 0.f, a5 = 0.f, a6 = 0.f, a7 = 0.f;

    #pragma unroll 8
    for (int j = rr.x; j < rr.y; ++j) {
        int2 ed = g_edges[j];
        float m = __int_as_float(ed.y);
        uint4 v = g_halfB[ed.x * 4 + c];
        float2 f;
        f = __half22float2(*reinterpret_cast<__half2*>(&v.x)); a0 += f.x * m; a1 += f.y * m;
        f = __half22float2(*reinterpret_cast<__half2*>(&v.y)); a2 += f.x * m; a3 += f.y * m;
        f = __half22float2(*reinterpret_cast<__half2*>(&v.z)); a4 += f.x * m; a5 += f.y * m;
        f = __half22float2(*reinterpret_cast<__half2*>(&v.w)); a6 += f.x * m; a7 += f.y * m;
    }

    float2 fac = g_fac[n];
    float dinv2 = fac.x, rsq = fac.y;

    int i0 = n * DV4 + c * 2;
    float4 p0 = g_scaled[i0], p1 = g_scaled[i0 + 1];       // s1
    float4 z0 = g_src32[i0], z1 = g_src32[i0 + 1];         // s0
    float4 s0, s1;                                          // s2
    s0.x = p0.x - a0 * dinv2; s0.y = p0.y - a1 * dinv2;
    s0.z = p0.z - a2 * dinv2; s0.w = p0.w - a3 * dinv2;
    s1.x = p1.x - a4 * dinv2; s1.y = p1.y - a5 * dinv2;
    s1.z = p1.z - a6 * dinv2; s1.w = p1.w - a7 * dinv2;
    g_scaled[i0] = s0;
    g_scaled[i0 + 1] = s1;

    float t0 = th0 * rsq, t1 = th1 * rsq, t2 = th2 * rsq;
    float4 h0, h1;
    h0.x = t0 * z0.x + t1 * p0.x + t2 * s0.x;
    h0.y = t0 * z0.y + t1 * p0.y + t2 * s0.y;
    h0.z = t0 * z0.z + t1 * p0.z + t2 * s0.z;
    h0.w = t0 * z0.w + t1 * p0.w + t2 * s0.w;
    h1.x = t0 * z1.x + t1 * p1.x + t2 * s1.x;
    h1.y = t0 * z1.y + t1 * p1.y + t2 * s1.y;
    h1.z = t0 * z1.z + t1 * p1.z + t2 * s1.z;
    h1.w = t0 * z1.w + t1 * p1.w + t2 * s1.w;
    h4[i0] = h0;
    h4[i0 + 1] = h1;

    uint4 hp;
    hp.x = h2u(__floats2half2_rn(s0.x, s0.y));
    hp.y = h2u(__floats2half2_rn(s0.z, s0.w));
    hp.z = h2u(__floats2half2_rn(s1.x, s1.y));
    hp.w = h2u(__floats2half2_rn(s1.z, s1.w));
    g_halfA[n * 4 + c] = hp;
}

// iterations 3-4: fp16 gather, in-place fp32 state, h accumulate.
// sel: 1 -> in=halfA out=halfB, 0 -> in=halfB out=halfA.
// last: restore zero-state invariant (g_cnt, g_degf, g_total).
__global__ void __launch_bounds__(256)
k_iter(float4* __restrict__ h4, float theta, int write_next, int sel, int last) {
    const uint4* __restrict__ gin  = sel ? g_halfA : g_halfB;
    uint4* __restrict__       gout = sel ? g_halfB : g_halfA;

    int t = threadIdx.x;
    int n = blockIdx.x * 64 + (t >> 2);
    if (n >= N_NODES) return;
    int c = t & 3;

    int2 rr = g_rows[n];

    float a0 = 0.f, a1 = 0.f, a2 = 0.f, a3 = 0.f;
    float a4 = 0.f, a5 = 0.f, a6 = 0.f, a7 = 0.f;

    #pragma unroll 8
    for (int j = rr.x; j < rr.y; ++j) {
        int2 ed = g_edges[j];
        float m = __int_as_float(ed.y);
        uint4 v = gin[ed.x * 4 + c];
        float2 f;
        f = __half22float2(*reinterpret_cast<__half2*>(&v.x)); a0 += f.x * m; a1 += f.y * m;
        f = __half22float2(*reinterpret_cast<__half2*>(&v.y)); a2 += f.x * m; a3 += f.y * m;
        f = __half22float2(*reinterpret_cast<__half2*>(&v.z)); a4 += f.x * m; a5 += f.y * m;
        f = __half22float2(*reinterpret_cast<__half2*>(&v.w)); a6 += f.x * m; a7 += f.y * m;
    }

    float2 fac = g_fac[n];
    float dinv2 = fac.x, rsq = fac.y;

    int i0 = n * DV4 + c * 2;
    float4 s0 = g_scaled[i0], s1 = g_scaled[i0 + 1];
    s0.x -= a0 * dinv2; s0.y -= a1 * dinv2; s0.z -= a2 * dinv2; s0.w -= a3 * dinv2;
    s1.x -= a4 * dinv2; s1.y -= a5 * dinv2; s1.z -= a6 * dinv2; s1.w -= a7 * dinv2;
    g_scaled[i0] = s0;
    g_scaled[i0 + 1] = s1;

    float tr = theta * rsq;
    float4 h0 = h4[i0], h1 = h4[i0 + 1];
    h0.x += tr * s0.x; h0.y += tr * s0.y; h0.z += tr * s0.z; h0.w += tr * s0.w;
    h1.x += tr * s1.x; h1.y += tr * s1.y; h1.z += tr * s1.z; h1.w += tr * s1.w;
    h4[i0] = h0;
    h4[i0 + 1] = h1;

    if (write_next) {
        uint4 hp;
        hp.x = h2u(__floats2half2_rn(s0.x, s0.y));
        hp.y = h2u(__floats2half2_rn(s0.z, s0.w));
        hp.z = h2u(__floats2half2_rn(s1.x, s1.y));
        hp.w = h2u(__floats2half2_rn(s1.z, s1.w));
        gout[n * 4 + c] = hp;
    }

    if (last && c == 0) {
        g_cnt[n] = 0;
        g_degf[n] = 0.0f;
        if (n == 0) g_total = 0;
    }
}

extern "C" void kernel_launch(void* const* d_in, const int* in_sizes, int n_in,
                              void* d_out, int out_size) {
    const float* feat = (const float*)d_in[0];
    const int*   src  = (const int*)d_in[1];
    const int*   dst  = (const int*)d_in[2];
    const float* mask = (const float*)d_in[3];
    float* out = (float*)d_out;

    const int E = in_sizes[1];
    const int TB = 256;

    // --- CSR build (scan-free) ---
    k_hist<<<(E + TB - 1) / TB, TB>>>(dst, mask, E);
    k_rows_init<<<(N_NODES + 255) / 256, 256>>>((const float4*)feat);
    k_scatter<<<(E + TB - 1) / TB, TB>>>(src, dst, mask, E);

    // --- 4 fused iterations ---  theta = {0.2, -0.4, 0.3, -0.15, 0.05}
    int node4_blocks = (N_NODES + 63) / 64;
    k_iter1<<<node4_blocks, TB>>>();                                  // s1, mirror B
    k_iter2<<<node4_blocks, TB>>>((float4*)out, 0.2f, -0.4f, 0.3f);   // h pure write, B->A
    k_iter<<<node4_blocks, TB>>>((float4*)out, -0.15f, 1, 1, 0);      // A->B
    k_iter<<<node4_blocks, TB>>>((float4*)out, 0.05f,  0, 0, 1);      // B, restore zeros
}

// round 15
// speedup vs baseline: 1.0002x; 1.0002x over previous
#include <cuda_runtime.h>
#include <cuda_fp16.h>
#include <cstdint>

// PolyConv: scan-free CSR build + atomic-free iterations.
// iter1: 8-lane groups, fp32 gather (1 wavefront/edge), h pure write.
// iters 2-4: 4-lane groups, fp16 gather mirrors (ping-pong), h RMW.
// Inputs: feat [N*32 f32], src [E i32], dst [E i32], mask [E f32]
// Output: h [N*32 f32]

#define N_NODES 100000
#define N_EDGES 1600000
#define DFEAT   32
#define DV4     (DFEAT / 4)        // 8 float4 per node row
#define NV4     (N_NODES * DV4)
#define NH4     (N_NODES * 4)      // 4 uint4 (8 halves) per node row

// ---- scratch (static __device__, zero-initialized; every call restores zeros) ----
__device__ int    g_cnt[N_NODES];        // in-degree; re-zeroed in iter4 tail
__device__ float  g_degf[N_NODES];       // mask-sum;  re-zeroed in iter4 tail
__device__ int    g_total;               // row allocator; re-zeroed in iter4 tail
__device__ int2   g_rows[N_NODES];       // {base, end} of node's CSR segment
__device__ int    g_cursor[N_NODES];
__device__ float2 g_fac[N_NODES];        // {dinv^2, sqrt(max(deg,1))}
__device__ int2   g_edges[N_EDGES];      // CSR: {src, mask_bits} grouped by dst
__device__ float4 g_src32[NV4];          // fp32 gather source for iter1 (T0 scaled)
__device__ float4 g_scaled[NV4];         // fp32 state, in-place (row-major)
__device__ uint4  g_halfA[NH4];          // fp16 gather mirror (ping)
__device__ uint4  g_halfB[NH4];          // fp16 gather mirror (pong)

static __device__ __forceinline__ unsigned h2u(__half2 h) {
    return *reinterpret_cast<unsigned*>(&h);
}

// ---------------------------------------------------------------------------
// histogram: edge count + mask-sum per dst (both start zero: invariant)
__global__ void k_hist(const int* __restrict__ dst, const float* __restrict__ mask, int E) {
    int e = blockIdx.x * blockDim.x + threadIdx.x;
    if (e < E) {
        int d = dst[e];
        atomicAdd(&g_cnt[d], 1);
        atomicAdd(&g_degf[d], mask[e]);
    }
}

// rows + factors + init fused.
// Phase 1 (thread per node): warp-aggregated atomic row allocation, fac from degf.
// Phase 2 (block-stride): src32 = feat * dinv (coalesced float4 writes).
__global__ void __launch_bounds__(256)
k_rows_init(const float4* __restrict__ feat4) {
    __shared__ float sh_dinv[256];
    int t = threadIdx.x;
    int lane = t & 31;
    int nb = blockIdx.x * 256;
    int n = nb + t;

    int cnt = (n < N_NODES) ? g_cnt[n] : 0;

    int incl = cnt;
    #pragma unroll
    for (int o = 1; o < 32; o <<= 1) {
        int y = __shfl_up_sync(0xFFFFFFFFu, incl, o);
        if (lane >= o) incl += y;
    }
    int warp_base = 0;
    if (lane == 31) warp_base = atomicAdd(&g_total, incl);
    warp_base = __shfl_sync(0xFFFFFFFFu, warp_base, 31);

    float dinv = 0.0f;
    if (n < N_NODES) {
        int base = warp_base + incl - cnt;
        g_rows[n] = make_int2(base, base + cnt);
        g_cursor[n] = base;
        float deg = fmaxf(g_degf[n], 1.0f);
        dinv = rsqrtf(deg);
        g_fac[n] = make_float2(dinv * dinv, deg * dinv);   // {dinv^2, sqrt(deg)}
    }
    sh_dinv[t] = dinv;
    __syncthreads();

    for (int i = t; i < 256 * DV4; i += 256) {
        int nn = nb + (i >> 3);
        if (nn >= N_NODES) break;
        float dv = sh_dinv[i >> 3];
        int idx = nn * DV4 + (i & 7);
        float4 f = feat4[idx];
        float4 s;
        s.x = f.x * dv; s.y = f.y * dv; s.z = f.z * dv; s.w = f.w * dv;
        g_src32[idx] = s;
    }
}

__global__ void k_scatter(const int* __restrict__ src, const int* __restrict__ dst,
                          const float* __restrict__ mask, int E) {
    int e = blockIdx.x * blockDim.x + threadIdx.x;
    if (e >= E) return;
    int d = dst[e];
    int pos = atomicAdd(&g_cursor[d], 1);
    g_edges[pos] = make_int2(src[e], __float_as_int(mask[e]));
}

// iteration 1: 8-lane groups; fp32 gather = ONE 128B-line instruction per edge.
// h pure write; writes fp32 state + fp16 mirror (uint2 per lane).
__global__ void __launch_bounds__(256)
k_iter1(float4* __restrict__ h4, float theta0, float theta1) {
    int t = threadIdx.x;
    int n = blockIdx.x * 32 + (t >> 3);    // 32 nodes per 256-thread block
    if (n >= N_NODES) return;
    int c = t & 7;                          // lane's float4 within the 8-float4 row

    int2 rr = g_rows[n];

    float a0 = 0.f, a1 = 0.f, a2 = 0.f, a3 = 0.f;

    #pragma unroll 4
    for (int j = rr.x; j < rr.y; ++j) {
        int2 ed = g_edges[j];               // broadcast across 8 lanes
        float m = __int_as_float(ed.y);
        float4 v = g_src32[ed.x * DV4 + c]; // 8 lanes -> one contiguous 128B line
        a0 += v.x * m; a1 += v.y * m; a2 += v.z * m; a3 += v.w * m;
    }

    float2 fac = g_fac[n];
    float dinv2 = fac.x, rsq = fac.y;

    int i = n * DV4 + c;
    float4 o = g_src32[i];
    float4 s;
    s.x = o.x - a0 * dinv2; s.y = o.y - a1 * dinv2;
    s.z = o.z - a2 * dinv2; s.w = o.w - a3 * dinv2;
    g_scaled[i] = s;

    float tpr = theta0 * rsq, tr = theta1 * rsq;
    float4 h;
    h.x = tpr * o.x + tr * s.x; h.y = tpr * o.y + tr * s.y;
    h.z = tpr * o.z + tr * s.z; h.w = tpr * o.w + tr * s.w;
    h4[i] = h;

    // fp16 mirror: this lane's 4 floats -> 2 half2 = uint2
    uint2 hp;
    hp.x = h2u(__floats2half2_rn(s.x, s.y));
    hp.y = h2u(__floats2half2_rn(s.z, s.w));
    reinterpret_cast<uint2*>(g_halfB)[n * 8 + c] = hp;
}

// iterations 2-4: 4-lane groups, fp16 gather, in-place fp32 state, h RMW.
// sel: 1 -> in=halfA out=halfB, 0 -> in=halfB out=halfA.
// last: restore zero-state invariant (g_cnt, g_degf, g_total).
__global__ void __launch_bounds__(256)
k_iter(float4* __restrict__ h4, float theta, int write_next, int sel, int last) {
    const uint4* __restrict__ gin  = sel ? g_halfA : g_halfB;
    uint4* __restrict__       gout = sel ? g_halfB : g_halfA;

    int t = threadIdx.x;
    int n = blockIdx.x * 64 + (t >> 2);
    if (n >= N_NODES) return;
    int c = t & 3;

    int2 rr = g_rows[n];

    float a0 = 0.f, a1 = 0.f, a2 = 0.f, a3 = 0.f;
    float a4 = 0.f, a5 = 0.f, a6 = 0.f, a7 = 0.f;

    #pragma unroll 8
    for (int j = rr.x; j < rr.y; ++j) {
        int2 ed = g_edges[j];
        float m = __int_as_float(ed.y);
        uint4 v = gin[ed.x * 4 + c];
        float2 f;
        f = __half22float2(*reinterpret_cast<__half2*>(&v.x)); a0 += f.x * m; a1 += f.y * m;
        f = __half22float2(*reinterpret_cast<__half2*>(&v.y)); a2 += f.x * m; a3 += f.y * m;
        f = __half22float2(*reinterpret_cast<__half2*>(&v.z)); a4 += f.x * m; a5 += f.y * m;
        f = __half22float2(*reinterpret_cast<__half2*>(&v.w)); a6 += f.x * m; a7 += f.y * m;
    }

    float2 fac = g_fac[n];
    float dinv2 = fac.x, rsq = fac.y;

    int i0 = n * DV4 + c * 2;
    float4 s0 = g_scaled[i0], s1 = g_scaled[i0 + 1];
    s0.x -= a0 * dinv2; s0.y -= a1 * dinv2; s0.z -= a2 * dinv2; s0.w -= a3 * dinv2;
    s1.x -= a4 * dinv2; s1.y -= a5 * dinv2; s1.z -= a6 * dinv2; s1.w -= a7 * dinv2;
    g_scaled[i0] = s0;
    g_scaled[i0 + 1] = s1;

    float tr = theta * rsq;
    float4 h0 = h4[i0], h1 = h4[i0 + 1];
    h0.x += tr * s0.x; h0.y += tr * s0.y; h0.z += tr * s0.z; h0.w += tr * s0.w;
    h1.x += tr * s1.x; h1.y += tr * s1.y; h1.z += tr * s1.z; h1.w += tr * s1.w;
    h4[i0] = h0;
    h4[i0 + 1] = h1;

    if (write_next) {
        uint4 hp;
        hp.x = h2u(__floats2half2_rn(s0.x, s0.y));
        hp.y = h2u(__floats2half2_rn(s0.z, s0.w));
        hp.z = h2u(__floats2half2_rn(s1.x, s1.y));
        hp.w = h2u(__floats2half2_rn(s1.z, s1.w));
        gout[n * 4 + c] = hp;
    }

    if (last && c == 0) {
        g_cnt[n] = 0;
        g_degf[n] = 0.0f;
        if (n == 0) g_total = 0;
    }
}

extern "C" void kernel_launch(void* const* d_in, const int* in_sizes, int n_in,
                              void* d_out, int out_size) {
    const float* feat = (const float*)d_in[0];
    const int*   src  = (const int*)d_in[1];
    const int*   dst  = (const int*)d_in[2];
    const float* mask = (const float*)d_in[3];
    float* out = (float*)d_out;

    const int E = in_sizes[1];
    const int TB = 256;

    // --- CSR build (scan-free) ---
    k_hist<<<(E + TB - 1) / TB, TB>>>(dst, mask, E);
    k_rows_init<<<(N_NODES + 255) / 256, 256>>>((const float4*)feat);
    k_scatter<<<(E + TB - 1) / TB, TB>>>(src, dst, mask, E);

    // --- 4 fused iterations ---  theta = {0.2, -0.4, 0.3, -0.15, 0.05}
    int node8_blocks = (N_NODES + 31) / 32;
    int node4_blocks = (N_NODES + 63) / 64;
    k_iter1<<<node8_blocks, TB>>>((float4*)out, 0.2f, -0.4f);     // h pure write, mirror B
    k_iter<<<node4_blocks, TB>>>((float4*)out, 0.3f,   1, 0, 0);  // B -> A
    k_iter<<<node4_blocks, TB>>>((float4*)out, -0.15f, 1, 1, 0);  // A -> B
    k_iter<<<node4_blocks, TB>>>((float4*)out, 0.05f,  0, 0, 1);  // B, restore zeros
}